// round 1
// baseline (speedup 1.0000x reference)
#include <cuda_runtime.h>
#include <cuda_fp16.h>
#include <cstdint>

#define BATCH 8192
#define DIM   1024
#define H1V   8
#define H2V   4
#define OUTD  256
#define K2DIM 4096   // DIM*H2
#define EPSV  1e-5f

// ---------------- scratch (device globals; no allocation) ----------------
__device__ __half g_h2[(size_t)BATCH * K2DIM];   // 64 MB, h2 pre-BN in fp16
__device__ __half g_wfc[OUTD * K2DIM];           // 2 MB, Wfc in fp16
__device__ float  g_p1s[8 * DIM],  g_p1q[8 * DIM];
__device__ float  g_a1[DIM * H1V], g_c1[DIM * H1V];
__device__ float  g_p2s[8 * K2DIM], g_p2q[8 * K2DIM];
__device__ float  g_a2[K2DIM], g_c2[K2DIM];

// ---------------- K0: Wfc fp32 -> fp16 ----------------
__global__ void k_wfc(const float* __restrict__ Wfc) {
    int i = blockIdx.x * 512 + threadIdx.x;   // grid 2048 x 512 = 1048576 exactly
    g_wfc[i] = __float2half(Wfc[i]);
}

// ---------------- K1: per-column sums of x (deterministic partials) ----------------
__global__ void k_stats1(const float* __restrict__ x) {
    int cg = blockIdx.x, rg = blockIdx.y, t = threadIdx.x;
    int dl = t & 63, rt = t >> 6;
    int d = cg * 64 + dl;
    float s = 0.f, q = 0.f;
    const float* p = x + (size_t)(rg * 1024 + rt) * DIM + d;
#pragma unroll 4
    for (int i = 0; i < 256; i++) {
        float v = p[(size_t)i * 4 * DIM];
        s += v; q = fmaf(v, v, q);
    }
    __shared__ float rs[4][64], rq[4][64];
    rs[rt][dl] = s; rq[rt][dl] = q;
    __syncthreads();
    if (t < 64) {
        float ss = rs[0][t] + rs[1][t] + rs[2][t] + rs[3][t];
        float qq = rq[0][t] + rq[1][t] + rq[2][t] + rq[3][t];
        g_p1s[rg * DIM + cg * 64 + t] = ss;
        g_p1q[rg * DIM + cg * 64 + t] = qq;
    }
}

// ---------------- K1b: finalize layer-1 affine coefficients ----------------
__global__ void k_fin1(const float* __restrict__ W1, const float* __restrict__ g1,
                       const float* __restrict__ be1) {
    int d = blockIdx.x * 256 + threadIdx.x;   // 4 x 256 = 1024
    if (d >= DIM) return;
    float s = 0.f, q = 0.f;
#pragma unroll
    for (int r = 0; r < 8; r++) { s += g_p1s[r * DIM + d]; q += g_p1q[r * DIM + d]; }
    float mx = s * (1.f / BATCH);
    float vx = fmaxf(q * (1.f / BATCH) - mx * mx, 0.f);
#pragma unroll
    for (int i = 0; i < H1V; i++) {
        int c = d * H1V + i;
        float w = W1[c];                       // W1[d][i][0]
        float a = g1[c] * w * rsqrtf(fmaf(w * w, vx, EPSV));
        g_a1[c] = a;
        g_c1[c] = be1[c] - a * mx;             // b1 cancels inside BN
    }
}

// ---------------- K2: fused y1 -> h2, store fp16 h2, channel stat partials ----------------
__global__ void k_layer2(const float* __restrict__ x, const float* __restrict__ W2) {
    int cg = blockIdx.x, rg = blockIdx.y, t = threadIdx.x;
    int dl = t & 63, rt = t >> 6;
    int d = cg * 64 + dl;

    __shared__ float sa[512], sc[512], sw[2048];
    for (int i = t; i < 512; i += 256)  { sa[i] = g_a1[cg * 512 + i]; sc[i] = g_c1[cg * 512 + i]; }
    for (int i = t; i < 2048; i += 256) { sw[i] = W2[cg * 2048 + i]; }
    __syncthreads();

    // hoist this thread's weights into registers (avoid LDS-bound inner loop)
    float a1r[8], c1r[8], w2r[4][8];
#pragma unroll
    for (int i = 0; i < 8; i++) { a1r[i] = sa[dl * 8 + i]; c1r[i] = sc[dl * 8 + i]; }
#pragma unroll
    for (int o = 0; o < 4; o++)
#pragma unroll
        for (int i = 0; i < 8; i++) w2r[o][i] = sw[dl * 32 + o * 8 + i];

    float s[4] = {0, 0, 0, 0}, q[4] = {0, 0, 0, 0};
#pragma unroll 2
    for (int it = 0; it < 256; it++) {
        int r = rg * 1024 + rt + it * 4;
        float xv = x[(size_t)r * DIM + d];
        float y[8];
#pragma unroll
        for (int i = 0; i < 8; i++) y[i] = fmaxf(fmaf(a1r[i], xv, c1r[i]), 0.f);
        float h[4];
#pragma unroll
        for (int o = 0; o < 4; o++) {
            float acc = 0.f;
#pragma unroll
            for (int i = 0; i < 8; i++) acc = fmaf(w2r[o][i], y[i], acc);
            h[o] = acc;
            s[o] += acc;
            q[o] = fmaf(acc, acc, q[o]);
        }
        __half2 h01 = __floats2half2_rn(h[0], h[1]);
        __half2 h23 = __floats2half2_rn(h[2], h[3]);
        uint2 pk;
        pk.x = *reinterpret_cast<uint32_t*>(&h01);
        pk.y = *reinterpret_cast<uint32_t*>(&h23);
        *reinterpret_cast<uint2*>(g_h2 + (size_t)r * K2DIM + d * 4) = pk;
    }

    __shared__ float red[4][64][8];
#pragma unroll
    for (int o = 0; o < 4; o++) { red[rt][dl][o] = s[o]; red[rt][dl][4 + o] = q[o]; }
    __syncthreads();
    if (t < 64) {
#pragma unroll
        for (int o = 0; o < 4; o++) {
            float ss = red[0][t][o] + red[1][t][o] + red[2][t][o] + red[3][t][o];
            float qq = red[0][t][4 + o] + red[1][t][4 + o] + red[2][t][4 + o] + red[3][t][4 + o];
            int c = (cg * 64 + t) * 4 + o;
            g_p2s[rg * K2DIM + c] = ss;
            g_p2q[rg * K2DIM + c] = qq;
        }
    }
}

// ---------------- K2b: finalize layer-2 affine coefficients ----------------
__global__ void k_fin2(const float* __restrict__ g2, const float* __restrict__ be2) {
    int c = blockIdx.x * 256 + threadIdx.x;    // 16 x 256 = 4096
    float s = 0.f, q = 0.f;
#pragma unroll
    for (int r = 0; r < 8; r++) { s += g_p2s[r * K2DIM + c]; q += g_p2q[r * K2DIM + c]; }
    float mu = s * (1.f / BATCH);
    float var = fmaxf(q * (1.f / BATCH) - mu * mu, 0.f);
    float a = g2[c] * rsqrtf(var + EPSV);
    g_a2[c] = a;
    g_c2[c] = be2[c] - a * mu;                  // b2 cancels inside BN
}

// ---------------- K3: out = relu(a2*h2+c2) @ Wfc^T + bfc (fp16 mma.sync) ----------------
__device__ __forceinline__ void ldsm_x4(uint32_t& r0, uint32_t& r1, uint32_t& r2, uint32_t& r3,
                                        uint32_t addr) {
    asm volatile("ldmatrix.sync.aligned.m8n8.x4.shared.b16 {%0,%1,%2,%3}, [%4];"
                 : "=r"(r0), "=r"(r1), "=r"(r2), "=r"(r3) : "r"(addr));
}
__device__ __forceinline__ void mma16816(float* c, const uint32_t a[4], uint32_t b0, uint32_t b1) {
    asm volatile(
        "mma.sync.aligned.m16n8k16.row.col.f32.f16.f16.f32 "
        "{%0,%1,%2,%3},{%4,%5,%6,%7},{%8,%9},{%0,%1,%2,%3};"
        : "+f"(c[0]), "+f"(c[1]), "+f"(c[2]), "+f"(c[3])
        : "r"(a[0]), "r"(a[1]), "r"(a[2]), "r"(a[3]), "r"(b0), "r"(b1));
}

#define AS_ELEMS (2 * 64 * 72)
#define BS_ELEMS (2 * 256 * 72)
#define GEMM_SMEM ((AS_ELEMS + BS_ELEMS) * 2 + 2 * K2DIM * 4)   // 124928 B

__global__ void __launch_bounds__(256, 1)
k_gemm(const float* __restrict__ bfc, float* __restrict__ out) {
    extern __shared__ char smraw[];
    __half* As = reinterpret_cast<__half*>(smraw);       // [2][64][72]
    __half* Bs = As + AS_ELEMS;                          // [2][256][72]
    float* a2s = reinterpret_cast<float*>(Bs + BS_ELEMS);
    float* c2s = a2s + K2DIM;

    const int t = threadIdx.x;
    const int bm = blockIdx.x * 64;
    const int warp = t >> 5, lane = t & 31;
    const int wm = warp >> 2, wn = warp & 3;             // warp tile: 32(m) x 64(n)

    for (int i = t; i < K2DIM; i += 256) { a2s[i] = g_a2[i]; c2s[i] = g_c2[i]; }

    const int arow = t >> 2, akoff = (t & 3) * 16;       // A: 64 rows x 64 k halves
    const __half* Agp = g_h2 + (size_t)(bm + arow) * K2DIM + akoff;
    const __half* Bgp = g_wfc + (size_t)t * K2DIM;       // B: row n = t

    float acc[2][8][4];
#pragma unroll
    for (int a = 0; a < 2; a++)
#pragma unroll
        for (int b = 0; b < 8; b++)
#pragma unroll
            for (int c = 0; c < 4; c++) acc[a][b][c] = 0.f;

    uint4 av[2], bv[8];

    auto store_chunk = [&](int buf, int kbase) {
        __half* ad = As + buf * (64 * 72) + arow * 72 + akoff;
#pragma unroll
        for (int j = 0; j < 2; j++) {
            uint4 v = av[j];
            __half2* hp = reinterpret_cast<__half2*>(&v);
            int kb = kbase + akoff + j * 8;
#pragma unroll
            for (int e = 0; e < 4; e++) {
                float2 f = __half22float2(hp[e]);
                int k = kb + e * 2;
                f.x = fmaxf(fmaf(a2s[k], f.x, c2s[k]), 0.f);
                f.y = fmaxf(fmaf(a2s[k + 1], f.y, c2s[k + 1]), 0.f);
                hp[e] = __floats2half2_rn(f.x, f.y);
            }
            *reinterpret_cast<uint4*>(ad + j * 8) = v;
        }
        __half* bd = Bs + buf * (256 * 72) + t * 72;
#pragma unroll
        for (int j = 0; j < 8; j++) *reinterpret_cast<uint4*>(bd + j * 8) = bv[j];
    };

    // prologue: chunk 0
    av[0] = *reinterpret_cast<const uint4*>(Agp);
    av[1] = *reinterpret_cast<const uint4*>(Agp + 8);
#pragma unroll
    for (int j = 0; j < 8; j++) bv[j] = *reinterpret_cast<const uint4*>(Bgp + j * 8);
    __syncthreads();                 // a2s/c2s ready
    store_chunk(0, 0);
    __syncthreads();

    const int a_lrow = lane & 15;
    const int a_ksel = ((lane >> 4) & 1) << 3;
    const int b_lrow = (lane & 7) + ((lane & 16) >> 1);
    const int b_ksel = lane & 8;

    for (int kc = 0; kc < 64; kc++) {
        int cur = kc & 1;
        if (kc < 63) {
            const __half* ag = Agp + (kc + 1) * 64;
            av[0] = *reinterpret_cast<const uint4*>(ag);
            av[1] = *reinterpret_cast<const uint4*>(ag + 8);
            const __half* bg = Bgp + (kc + 1) * 64;
#pragma unroll
            for (int j = 0; j < 8; j++) bv[j] = *reinterpret_cast<const uint4*>(bg + j * 8);
        }
        const __half* Ac = As + cur * (64 * 72);
        const __half* Bc = Bs + cur * (256 * 72);
#pragma unroll
        for (int ks = 0; ks < 4; ks++) {
            int kb = ks * 16;
            uint32_t af[2][4];
#pragma unroll
            for (int mt = 0; mt < 2; mt++) {
                int row = wm * 32 + mt * 16 + a_lrow;
                uint32_t addr = (uint32_t)__cvta_generic_to_shared(Ac + row * 72 + kb + a_ksel);
                ldsm_x4(af[mt][0], af[mt][1], af[mt][2], af[mt][3], addr);
            }
#pragma unroll
            for (int p = 0; p < 4; p++) {
                int nrow = wn * 64 + p * 16 + b_lrow;
                uint32_t addr = (uint32_t)__cvta_generic_to_shared(Bc + nrow * 72 + kb + b_ksel);
                uint32_t b0, b1, b2, b3;
                ldsm_x4(b0, b1, b2, b3, addr);
#pragma unroll
                for (int mt = 0; mt < 2; mt++) {
                    mma16816(acc[mt][2 * p], af[mt], b0, b1);
                    mma16816(acc[mt][2 * p + 1], af[mt], b2, b3);
                }
            }
        }
        if (kc < 63) store_chunk(1 - cur, (kc + 1) * 64);
        __syncthreads();
    }

    // epilogue
#pragma unroll
    for (int mt = 0; mt < 2; mt++) {
        int r0 = bm + wm * 32 + mt * 16 + (lane >> 2);
#pragma unroll
        for (int nt = 0; nt < 8; nt++) {
            int cc = wn * 64 + nt * 8 + ((lane & 3) << 1);
            float bl = bfc[cc], bh = bfc[cc + 1];
            float2 v0 = make_float2(acc[mt][nt][0] + bl, acc[mt][nt][1] + bh);
            float2 v1 = make_float2(acc[mt][nt][2] + bl, acc[mt][nt][3] + bh);
            *reinterpret_cast<float2*>(out + (size_t)r0 * OUTD + cc) = v0;
            *reinterpret_cast<float2*>(out + (size_t)(r0 + 8) * OUTD + cc) = v1;
        }
    }
}

// ---------------- launch ----------------
extern "C" void kernel_launch(void* const* d_in, const int* in_sizes, int n_in,
                              void* d_out, int out_size) {
    const float* x   = (const float*)d_in[0];
    const float* W1  = (const float*)d_in[1];
    const float* g1  = (const float*)d_in[3];
    const float* be1 = (const float*)d_in[4];
    const float* W2  = (const float*)d_in[5];
    const float* g2  = (const float*)d_in[7];
    const float* be2 = (const float*)d_in[8];
    const float* Wfc = (const float*)d_in[9];
    const float* bfc = (const float*)d_in[10];
    float* out = (float*)d_out;

    cudaFuncSetAttribute(k_gemm, cudaFuncAttributeMaxDynamicSharedMemorySize, GEMM_SMEM);

    k_wfc<<<2048, 512>>>(Wfc);
    k_stats1<<<dim3(16, 8), 256>>>(x);
    k_fin1<<<4, 256>>>(W1, g1, be1);
    k_layer2<<<dim3(16, 8), 256>>>(x, W2);
    k_fin2<<<16, 256>>>(g2, be2);
    k_gemm<<<128, 256, GEMM_SMEM>>>(bfc, out);
}

// round 5
// speedup vs baseline: 1.2631x; 1.2631x over previous
#include <cuda_runtime.h>
#include <cuda_fp16.h>
#include <cstdint>

#define BATCH 8192
#define DIM   1024
#define H1V   8
#define H2V   4
#define OUTD  256
#define K2DIM 4096   // DIM*H2
#define EPSV  1e-5f
#define RG1   32     // row groups for stats1 partials
#define RG2   32     // row groups for layer2 partials

// ---------------- scratch (device globals; no allocation) ----------------
__device__ __half g_h2[(size_t)BATCH * K2DIM];   // 64 MB, h2 pre-BN in fp16
__device__ __half g_wfc[OUTD * K2DIM];           // 2 MB, Wfc in fp16
__device__ float  g_p1s[RG1 * DIM],  g_p1q[RG1 * DIM];
__device__ float  g_a1[DIM * H1V], g_c1[DIM * H1V];
__device__ float  g_p2s[RG2 * K2DIM], g_p2q[RG2 * K2DIM];
__device__ float  g_a2[K2DIM], g_c2[K2DIM];

// ---------------- K0: Wfc fp32 -> fp16 ----------------
__global__ void k_wfc(const float* __restrict__ Wfc) {
    int i = blockIdx.x * 512 + threadIdx.x;   // grid 2048 x 512 = 1048576 exactly
    g_wfc[i] = __float2half(Wfc[i]);
}

// ---------------- K1: per-column sums of x (deterministic partials) ----------------
// grid (8, 32), block 256. Each block: 128 cols (float4 per thread) x 256 rows.
__global__ void k_stats1(const float* __restrict__ x) {
    int cg = blockIdx.x, rg = blockIdx.y, t = threadIdx.x;
    int cl = t & 31, rt = t >> 5;             // 32 col-threads x 8 row-threads
    int d = cg * 128 + cl * 4;
    float4 s = make_float4(0.f, 0.f, 0.f, 0.f);
    float4 q = make_float4(0.f, 0.f, 0.f, 0.f);
    const float4* p = reinterpret_cast<const float4*>(
        x + (size_t)(rg * 256 + rt) * DIM + d);
#pragma unroll 8
    for (int i = 0; i < 32; i++) {
        float4 v = p[(size_t)i * 8 * (DIM / 4)];
        s.x += v.x; q.x = fmaf(v.x, v.x, q.x);
        s.y += v.y; q.y = fmaf(v.y, v.y, q.y);
        s.z += v.z; q.z = fmaf(v.z, v.z, q.z);
        s.w += v.w; q.w = fmaf(v.w, v.w, q.w);
    }
    __shared__ float rs[8][128], rq[8][128];
    rs[rt][cl * 4 + 0] = s.x; rq[rt][cl * 4 + 0] = q.x;
    rs[rt][cl * 4 + 1] = s.y; rq[rt][cl * 4 + 1] = q.y;
    rs[rt][cl * 4 + 2] = s.z; rq[rt][cl * 4 + 2] = q.z;
    rs[rt][cl * 4 + 3] = s.w; rq[rt][cl * 4 + 3] = q.w;
    __syncthreads();
    if (t < 128) {
        float ss = 0.f, qq = 0.f;
#pragma unroll
        for (int r = 0; r < 8; r++) { ss += rs[r][t]; qq += rq[r][t]; }
        g_p1s[rg * DIM + cg * 128 + t] = ss;
        g_p1q[rg * DIM + cg * 128 + t] = qq;
    }
}

// ---------------- K1b: finalize layer-1 affine coefficients ----------------
__global__ void k_fin1(const float* __restrict__ W1, const float* __restrict__ g1,
                       const float* __restrict__ be1) {
    int d = blockIdx.x * 256 + threadIdx.x;   // 4 x 256 = 1024
    if (d >= DIM) return;
    float s = 0.f, q = 0.f;
#pragma unroll
    for (int r = 0; r < RG1; r++) { s += g_p1s[r * DIM + d]; q += g_p1q[r * DIM + d]; }
    float mx = s * (1.f / BATCH);
    float vx = fmaxf(q * (1.f / BATCH) - mx * mx, 0.f);
#pragma unroll
    for (int i = 0; i < H1V; i++) {
        int c = d * H1V + i;
        float w = W1[c];                       // W1[d][i][0]
        float a = g1[c] * w * rsqrtf(fmaf(w * w, vx, EPSV));
        g_a1[c] = a;
        g_c1[c] = be1[c] - a * mx;             // b1 cancels inside BN
    }
}

// ---------------- K2: fused y1 -> h2, store fp16 h2, channel stat partials ----------------
// grid (16, 32), block 256. Each block: 64 cols x 256 rows. Manual unroll-4 (MLP=4).
__global__ void __launch_bounds__(256)
k_layer2(const float* __restrict__ x, const float* __restrict__ W2) {
    int cg = blockIdx.x, rg = blockIdx.y, t = threadIdx.x;
    int dl = t & 63, rt = t >> 6;
    int d = cg * 64 + dl;

    __shared__ float sa[512], sc[512], sw[2048];
    for (int i = t; i < 512; i += 256)  { sa[i] = g_a1[cg * 512 + i]; sc[i] = g_c1[cg * 512 + i]; }
    for (int i = t; i < 2048; i += 256) { sw[i] = W2[cg * 2048 + i]; }
    __syncthreads();

    // hoist this thread's weights into registers
    float a1r[8], c1r[8], w2r[4][8];
#pragma unroll
    for (int i = 0; i < 8; i++) { a1r[i] = sa[dl * 8 + i]; c1r[i] = sc[dl * 8 + i]; }
#pragma unroll
    for (int o = 0; o < 4; o++)
#pragma unroll
        for (int i = 0; i < 8; i++) w2r[o][i] = sw[dl * 32 + o * 8 + i];

    float s[4] = {0, 0, 0, 0}, q[4] = {0, 0, 0, 0};
    const int rbase = rg * 256 + rt;

#pragma unroll 1
    for (int it = 0; it < 64; it += 4) {
        float xv[4];
#pragma unroll
        for (int u = 0; u < 4; u++)
            xv[u] = x[(size_t)(rbase + (it + u) * 4) * DIM + d];
#pragma unroll
        for (int u = 0; u < 4; u++) {
            int r = rbase + (it + u) * 4;
            float y[8];
#pragma unroll
            for (int i = 0; i < 8; i++) y[i] = fmaxf(fmaf(a1r[i], xv[u], c1r[i]), 0.f);
            float h[4];
#pragma unroll
            for (int o = 0; o < 4; o++) {
                float acc = 0.f;
#pragma unroll
                for (int i = 0; i < 8; i++) acc = fmaf(w2r[o][i], y[i], acc);
                h[o] = acc;
                s[o] += acc;
                q[o] = fmaf(acc, acc, q[o]);
            }
            __half2 h01 = __floats2half2_rn(h[0], h[1]);
            __half2 h23 = __floats2half2_rn(h[2], h[3]);
            uint2 pk;
            pk.x = *reinterpret_cast<uint32_t*>(&h01);
            pk.y = *reinterpret_cast<uint32_t*>(&h23);
            *reinterpret_cast<uint2*>(g_h2 + (size_t)r * K2DIM + d * 4) = pk;
        }
    }

    __shared__ float red[4][64][8];
#pragma unroll
    for (int o = 0; o < 4; o++) { red[rt][dl][o] = s[o]; red[rt][dl][4 + o] = q[o]; }
    __syncthreads();
    if (t < 64) {
#pragma unroll
        for (int o = 0; o < 4; o++) {
            float ss = red[0][t][o] + red[1][t][o] + red[2][t][o] + red[3][t][o];
            float qq = red[0][t][4 + o] + red[1][t][4 + o] + red[2][t][4 + o] + red[3][t][4 + o];
            int c = (cg * 64 + t) * 4 + o;
            g_p2s[rg * K2DIM + c] = ss;
            g_p2q[rg * K2DIM + c] = qq;
        }
    }
}

// ---------------- K2b: finalize layer-2 affine coefficients ----------------
__global__ void k_fin2(const float* __restrict__ g2, const float* __restrict__ be2) {
    int c = blockIdx.x * 256 + threadIdx.x;    // 16 x 256 = 4096
    float s = 0.f, q = 0.f;
#pragma unroll
    for (int r = 0; r < RG2; r++) { s += g_p2s[r * K2DIM + c]; q += g_p2q[r * K2DIM + c]; }
    float mu = s * (1.f / BATCH);
    float var = fmaxf(q * (1.f / BATCH) - mu * mu, 0.f);
    float a = g2[c] * rsqrtf(var + EPSV);
    g_a2[c] = a;
    g_c2[c] = be2[c] - a * mu;                  // b2 cancels inside BN
}

// ---------------- K3: out = relu(a2*h2+c2) @ Wfc^T + bfc (fp16 mma.sync) ----------------
__device__ __forceinline__ void ldsm_x4(uint32_t& r0, uint32_t& r1, uint32_t& r2, uint32_t& r3,
                                        uint32_t addr) {
    asm volatile("ldmatrix.sync.aligned.m8n8.x4.shared.b16 {%0,%1,%2,%3}, [%4];"
                 : "=r"(r0), "=r"(r1), "=r"(r2), "=r"(r3) : "r"(addr));
}
__device__ __forceinline__ void mma16816(float* c, const uint32_t a[4], uint32_t b0, uint32_t b1) {
    asm volatile(
        "mma.sync.aligned.m16n8k16.row.col.f32.f16.f16.f32 "
        "{%0,%1,%2,%3},{%4,%5,%6,%7},{%8,%9},{%0,%1,%2,%3};"
        : "+f"(c[0]), "+f"(c[1]), "+f"(c[2]), "+f"(c[3])
        : "r"(a[0]), "r"(a[1]), "r"(a[2]), "r"(a[3]), "r"(b0), "r"(b1));
}

#define AS_ELEMS (2 * 64 * 72)
#define BS_ELEMS (2 * 256 * 72)
#define GEMM_SMEM ((AS_ELEMS + BS_ELEMS) * 2 + 2 * K2DIM * 4)   // 124928 B

__global__ void __launch_bounds__(256, 1)
k_gemm(const float* __restrict__ bfc, float* __restrict__ out) {
    extern __shared__ char smraw[];
    __half* As = reinterpret_cast<__half*>(smraw);       // [2][64][72]
    __half* Bs = As + AS_ELEMS;                          // [2][256][72]
    float* a2s = reinterpret_cast<float*>(Bs + BS_ELEMS);
    float* c2s = a2s + K2DIM;

    const int t = threadIdx.x;
    const int bm = blockIdx.x * 64;
    const int warp = t >> 5, lane = t & 31;
    const int wm = warp >> 2, wn = warp & 3;             // warp tile: 32(m) x 64(n)

    for (int i = t; i < K2DIM; i += 256) { a2s[i] = g_a2[i]; c2s[i] = g_c2[i]; }

    const int arow = t >> 2, akoff = (t & 3) * 16;       // A: 64 rows x 64 k halves
    const __half* Agp = g_h2 + (size_t)(bm + arow) * K2DIM + akoff;
    const __half* Bgp = g_wfc + (size_t)t * K2DIM;       // B: row n = t

    float acc[2][8][4];
#pragma unroll
    for (int a = 0; a < 2; a++)
#pragma unroll
        for (int b = 0; b < 8; b++)
#pragma unroll
            for (int c = 0; c < 4; c++) acc[a][b][c] = 0.f;

    uint4 av[2], bv[8];

    auto store_chunk = [&](int buf, int kbase) {
        __half* ad = As + buf * (64 * 72) + arow * 72 + akoff;
#pragma unroll
        for (int j = 0; j < 2; j++) {
            uint4 v = av[j];
            __half2* hp = reinterpret_cast<__half2*>(&v);
            int kb = kbase + akoff + j * 8;
#pragma unroll
            for (int e = 0; e < 4; e++) {
                float2 f = __half22float2(hp[e]);
                int k = kb + e * 2;
                f.x = fmaxf(fmaf(a2s[k], f.x, c2s[k]), 0.f);
                f.y = fmaxf(fmaf(a2s[k + 1], f.y, c2s[k + 1]), 0.f);
                hp[e] = __floats2half2_rn(f.x, f.y);
            }
            *reinterpret_cast<uint4*>(ad + j * 8) = v;
        }
        __half* bd = Bs + buf * (256 * 72) + t * 72;
#pragma unroll
        for (int j = 0; j < 8; j++) *reinterpret_cast<uint4*>(bd + j * 8) = bv[j];
    };

    // prologue: chunk 0
    av[0] = *reinterpret_cast<const uint4*>(Agp);
    av[1] = *reinterpret_cast<const uint4*>(Agp + 8);
#pragma unroll
    for (int j = 0; j < 8; j++) bv[j] = *reinterpret_cast<const uint4*>(Bgp + j * 8);
    __syncthreads();                 // a2s/c2s ready
    store_chunk(0, 0);
    __syncthreads();

    const int a_lrow = lane & 15;
    const int a_ksel = ((lane >> 4) & 1) << 3;
    const int b_lrow = (lane & 7) + ((lane & 16) >> 1);
    const int b_ksel = lane & 8;

    for (int kc = 0; kc < 64; kc++) {
        int cur = kc & 1;
        if (kc < 63) {
            const __half* ag = Agp + (kc + 1) * 64;
            av[0] = *reinterpret_cast<const uint4*>(ag);
            av[1] = *reinterpret_cast<const uint4*>(ag + 8);
            const __half* bg = Bgp + (kc + 1) * 64;
#pragma unroll
            for (int j = 0; j < 8; j++) bv[j] = *reinterpret_cast<const uint4*>(bg + j * 8);
        }
        const __half* Ac = As + cur * (64 * 72);
        const __half* Bc = Bs + cur * (256 * 72);
#pragma unroll
        for (int ks = 0; ks < 4; ks++) {
            int kb = ks * 16;
            uint32_t af[2][4];
#pragma unroll
            for (int mt = 0; mt < 2; mt++) {
                int row = wm * 32 + mt * 16 + a_lrow;
                uint32_t addr = (uint32_t)__cvta_generic_to_shared(Ac + row * 72 + kb + a_ksel);
                ldsm_x4(af[mt][0], af[mt][1], af[mt][2], af[mt][3], addr);
            }
#pragma unroll
            for (int p = 0; p < 4; p++) {
                int nrow = wn * 64 + p * 16 + b_lrow;
                uint32_t addr = (uint32_t)__cvta_generic_to_shared(Bc + nrow * 72 + kb + b_ksel);
                uint32_t b0, b1, b2, b3;
                ldsm_x4(b0, b1, b2, b3, addr);
#pragma unroll
                for (int mt = 0; mt < 2; mt++) {
                    mma16816(acc[mt][2 * p], af[mt], b0, b1);
                    mma16816(acc[mt][2 * p + 1], af[mt], b2, b3);
                }
            }
        }
        if (kc < 63) store_chunk(1 - cur, (kc + 1) * 64);
        __syncthreads();
    }

    // epilogue
#pragma unroll
    for (int mt = 0; mt < 2; mt++) {
        int r0 = bm + wm * 32 + mt * 16 + (lane >> 2);
#pragma unroll
        for (int nt = 0; nt < 8; nt++) {
            int cc = wn * 64 + nt * 8 + ((lane & 3) << 1);
            float bl = bfc[cc], bh = bfc[cc + 1];
            float2 v0 = make_float2(acc[mt][nt][0] + bl, acc[mt][nt][1] + bh);
            float2 v1 = make_float2(acc[mt][nt][2] + bl, acc[mt][nt][3] + bh);
            *reinterpret_cast<float2*>(out + (size_t)r0 * OUTD + cc) = v0;
            *reinterpret_cast<float2*>(out + (size_t)(r0 + 8) * OUTD + cc) = v1;
        }
    }
}

// ---------------- launch ----------------
extern "C" void kernel_launch(void* const* d_in, const int* in_sizes, int n_in,
                              void* d_out, int out_size) {
    const float* x   = (const float*)d_in[0];
    const float* W1  = (const float*)d_in[1];
    const float* g1  = (const float*)d_in[3];
    const float* be1 = (const float*)d_in[4];
    const float* W2  = (const float*)d_in[5];
    const float* g2  = (const float*)d_in[7];
    const float* be2 = (const float*)d_in[8];
    const float* Wfc = (const float*)d_in[9];
    const float* bfc = (const float*)d_in[10];
    float* out = (float*)d_out;

    cudaFuncSetAttribute(k_gemm, cudaFuncAttributeMaxDynamicSharedMemorySize, GEMM_SMEM);

    k_wfc<<<2048, 512>>>(Wfc);
    k_stats1<<<dim3(8, 32), 256>>>(x);
    k_fin1<<<4, 256>>>(W1, g1, be1);
    k_layer2<<<dim3(16, 32), 256>>>(x, W2);
    k_fin2<<<16, 256>>>(g2, be2);
    k_gemm<<<128, 256, GEMM_SMEM>>>(bfc, out);
}